// round 1
// baseline (speedup 1.0000x reference)
#include <cuda_runtime.h>
#include <math_constants.h>

// Problem dims
#define NB 64
#define NC 64
#define NH 64
#define NW 64
#define NK 512
#define NHW (NH*NW)          // 4096
#define NPTS (NB*NHW)        // 262144

// Output packing (order of reference return tuple, flattened, all float32):
// out[NB,NC,NH,NW], diff[1], ind[NB,NH,NW], new_embedding[NC,NK],
// new_cluster_size[NK], new_embedding_avg[NC,NK]
#define OFF_OUT  0
#define OFF_DIFF (NPTS*NC)              // 16777216
#define OFF_IND  (OFF_DIFF + 1)         // 16777217
#define OFF_EMB  (OFF_IND + NPTS)       // 17039361
#define OFF_CS   (OFF_EMB + NC*NK)      // 17072129
#define OFF_EAVG (OFF_CS + NK)          // 17072641

// Scratch (allocation-free rule: __device__ globals)
__device__ float g_halfnorm[NK];
__device__ int   g_ind[NPTS];
__device__ float g_counts[NK];
__device__ float g_esum[NC*NK];
__device__ float g_diff;

// ---------------------------------------------------------------------------
// K0: zero scratch + precompute 0.5*||e_k||^2
// ---------------------------------------------------------------------------
__global__ void vq_prep(const float* __restrict__ emb) {
    int tid = blockIdx.x*blockDim.x + threadIdx.x;
    int stride = gridDim.x*blockDim.x;
    for (int i = tid; i < NC*NK; i += stride) g_esum[i] = 0.f;
    for (int i = tid; i < NK; i += stride) g_counts[i] = 0.f;
    if (tid == 0) g_diff = 0.f;
    if (tid < NK) {
        float s = 0.f;
        #pragma unroll 8
        for (int c = 0; c < NC; c++) {
            float v = emb[c*NK + tid];
            s = fmaf(v, v, s);
        }
        g_halfnorm[tid] = 0.5f*s;
    }
}

// ---------------------------------------------------------------------------
// K1: argmin over codes (GEMM+argmax), quantize gather -> out, diff partials
//     One thread == one point; x[64] in registers; embedding staged in smem
//     in K-chunks of 128 (transposed, padded rows, float4 broadcast loads).
// ---------------------------------------------------------------------------
#define KC  128
#define TPB 256

__global__ __launch_bounds__(TPB) void vq_argmin(
    const float* __restrict__ input, const float* __restrict__ emb,
    float* __restrict__ out, float* __restrict__ ind_out)
{
    __shared__ float e_sm[KC][68];   // row stride 68 floats (272B, 16B aligned)
    __shared__ float hn_sm[KC];
    __shared__ float red_sm[TPB/32];

    int n  = blockIdx.x*TPB + threadIdx.x;
    int b  = n >> 12;        // n / 4096
    int hw = n & 4095;
    const float* xp = input + b*NC*NHW + hw;

    float x[NC];
    #pragma unroll
    for (int c = 0; c < NC; c++) x[c] = xp[c*NHW];  // coalesced across warp

    float best = -CUDART_INF_F;
    int bestk = 0;

    for (int k0 = 0; k0 < NK; k0 += KC) {
        __syncthreads();
        // Stage transposed tile: e_sm[k][c] = emb[c][k0+k]; global reads coalesced
        for (int i = threadIdx.x; i < NC*KC; i += TPB) {
            int c = i >> 7;
            int k = i & (KC-1);
            e_sm[k][c] = emb[c*NK + k0 + k];
        }
        if (threadIdx.x < KC) hn_sm[threadIdx.x] = g_halfnorm[k0 + threadIdx.x];
        __syncthreads();

        for (int k = 0; k < KC; k += 4) {
            float a0 = -hn_sm[k+0];
            float a1 = -hn_sm[k+1];
            float a2 = -hn_sm[k+2];
            float a3 = -hn_sm[k+3];
            #pragma unroll
            for (int c = 0; c < NC; c += 4) {
                float4 e0 = *(const float4*)&e_sm[k+0][c];
                float4 e1 = *(const float4*)&e_sm[k+1][c];
                float4 e2 = *(const float4*)&e_sm[k+2][c];
                float4 e3 = *(const float4*)&e_sm[k+3][c];
                a0 = fmaf(x[c],e0.x,a0); a0 = fmaf(x[c+1],e0.y,a0);
                a0 = fmaf(x[c+2],e0.z,a0); a0 = fmaf(x[c+3],e0.w,a0);
                a1 = fmaf(x[c],e1.x,a1); a1 = fmaf(x[c+1],e1.y,a1);
                a1 = fmaf(x[c+2],e1.z,a1); a1 = fmaf(x[c+3],e1.w,a1);
                a2 = fmaf(x[c],e2.x,a2); a2 = fmaf(x[c+1],e2.y,a2);
                a2 = fmaf(x[c+2],e2.z,a2); a2 = fmaf(x[c+3],e2.w,a2);
                a3 = fmaf(x[c],e3.x,a3); a3 = fmaf(x[c+1],e3.y,a3);
                a3 = fmaf(x[c+2],e3.z,a3); a3 = fmaf(x[c+3],e3.w,a3);
            }
            // strict > keeps the earliest index on ties (matches jnp.argmin)
            if (a0 > best) { best = a0; bestk = k0+k+0; }
            if (a1 > best) { best = a1; bestk = k0+k+1; }
            if (a2 > best) { best = a2; bestk = k0+k+2; }
            if (a3 > best) { best = a3; bestk = k0+k+3; }
        }
    }

    g_ind[n]   = bestk;
    ind_out[n] = (float)bestk;

    // Gather chosen code column (embedding is L1/L2 resident), write NCHW out,
    // accumulate commitment-loss partial.
    float* op = out + b*NC*NHW + hw;
    float dsum = 0.f;
    #pragma unroll
    for (int c = 0; c < NC; c++) {
        float q = __ldg(&emb[c*NK + bestk]);
        op[c*NHW] = q;
        float t = q - x[c];
        dsum = fmaf(t, t, dsum);
    }
    #pragma unroll
    for (int o = 16; o; o >>= 1) dsum += __shfl_down_sync(0xffffffffu, dsum, o);
    if ((threadIdx.x & 31) == 0) red_sm[threadIdx.x >> 5] = dsum;
    __syncthreads();
    if (threadIdx.x == 0) {
        float s = 0.f;
        #pragma unroll
        for (int w = 0; w < TPB/32; w++) s += red_sm[w];
        atomicAdd(&g_diff, s);
    }
}

// ---------------------------------------------------------------------------
// K2: counts + segment-sum (flat^T @ onehot) via per-block smem accumulators
// ---------------------------------------------------------------------------
#define SC_TPB 256
#define KPAD   513   // pad K to break the stride-512 bank pattern
#define SC_GRID 148

__global__ __launch_bounds__(SC_TPB) void vq_scatter(const float* __restrict__ input) {
    extern __shared__ float acc[];           // [NC][KPAD] + cnt[NK]
    float* cnt = acc + NC*KPAD;
    for (int i = threadIdx.x; i < NC*KPAD + NK; i += SC_TPB) acc[i] = 0.f;
    __syncthreads();

    int stride = gridDim.x*SC_TPB;
    for (int n = blockIdx.x*SC_TPB + threadIdx.x; n < NPTS; n += stride) {
        int ind = g_ind[n];
        int b  = n >> 12;
        int hw = n & 4095;
        const float* xp = input + b*NC*NHW + hw;
        atomicAdd(&cnt[ind], 1.f);
        #pragma unroll
        for (int c = 0; c < NC; c++)
            atomicAdd(&acc[c*KPAD + ind], xp[c*NHW]);
    }
    __syncthreads();

    for (int i = threadIdx.x; i < NC*NK; i += SC_TPB)
        atomicAdd(&g_esum[i], acc[(i >> 9)*KPAD + (i & 511)]);
    for (int i = threadIdx.x; i < NK; i += SC_TPB)
        atomicAdd(&g_counts[i], cnt[i]);
}

// ---------------------------------------------------------------------------
// K3: EMA updates, normalization, final scalar writes
// ---------------------------------------------------------------------------
__global__ void vq_finalize(const float* __restrict__ cs,
                            const float* __restrict__ eavg,
                            float* __restrict__ d_out)
{
    __shared__ float red[16];
    int k = threadIdx.x;                 // 512 threads
    float ncs = fmaf(cs[k], 0.99f, 0.01f*g_counts[k]);
    d_out[OFF_CS + k] = ncs;

    float s = ncs;
    #pragma unroll
    for (int o = 16; o; o >>= 1) s += __shfl_down_sync(0xffffffffu, s, o);
    if ((k & 31) == 0) red[k >> 5] = s;
    __syncthreads();
    if (k < 32) {
        float v = (k < 16) ? red[k] : 0.f;
        #pragma unroll
        for (int o = 8; o; o >>= 1) v += __shfl_down_sync(0xffffffffu, v, o);
        if (k == 0) red[0] = v;
    }
    __syncthreads();
    float tot = red[0];
    float csk = (ncs + 1e-5f) / (tot + 512.f*1e-5f) * tot;
    float inv = 1.f/csk;

    for (int c = 0; c < NC; c++) {
        int i = c*NK + k;
        float na = fmaf(eavg[i], 0.99f, 0.01f*g_esum[i]);
        d_out[OFF_EAVG + i] = na;
        d_out[OFF_EMB  + i] = na*inv;
    }
    if (k == 0) d_out[OFF_DIFF] = g_diff * (1.f/(float)(NPTS*NC));
}

// ---------------------------------------------------------------------------
extern "C" void kernel_launch(void* const* d_in, const int* in_sizes, int n_in,
                              void* d_out, int out_size) {
    const float* input = (const float*)d_in[0];  // [B,C,H,W]
    const float* emb   = (const float*)d_in[1];  // [C,K]
    const float* cs    = (const float*)d_in[2];  // [K]
    const float* eavg  = (const float*)d_in[3];  // [C,K]
    float* out = (float*)d_out;

    const size_t sc_smem = (size_t)(NC*KPAD + NK)*sizeof(float);  // 133376 B
    cudaFuncSetAttribute(vq_scatter, cudaFuncAttributeMaxDynamicSharedMemorySize,
                         (int)sc_smem);

    vq_prep<<<64, 512>>>(emb);
    vq_argmin<<<NPTS/TPB, TPB>>>(input, emb, out + OFF_OUT, out + OFF_IND);
    vq_scatter<<<SC_GRID, SC_TPB, sc_smem>>>(input);
    vq_finalize<<<1, NK>>>(cs, eavg, out);
}

// round 2
// speedup vs baseline: 1.1711x; 1.1711x over previous
#include <cuda_runtime.h>
#include <math_constants.h>

// Problem dims
#define NB 64
#define NC 64
#define NH 64
#define NW 64
#define NK 512
#define NHW (NH*NW)          // 4096
#define NPTS (NB*NHW)        // 262144
#define NTILES (NPTS/256)    // 1024

// Output packing (flattened reference tuple, all float32)
#define OFF_OUT  0
#define OFF_DIFF (NPTS*NC)
#define OFF_IND  (OFF_DIFF + 1)
#define OFF_EMB  (OFF_IND + NPTS)
#define OFF_CS   (OFF_EMB + NC*NK)
#define OFF_EAVG (OFF_CS + NK)

#define GRID 148
#define TPB  256
#define KC   256             // k-chunk staged in smem
#define ROWS 260             // e_sm row stride (floats), 1040B: 16B-aligned
#define KPAD 513             // accumulator row pad

// Scratch (__device__ globals; no allocation allowed)
__device__ float g_neghn[NK];                 // -0.5*||e_k||^2
__device__ float g_part[GRID*NC*NK];          // per-block embedding-sum partials
__device__ float g_pcnt[GRID*NK];             // per-block count partials
__device__ float g_inv[NK];                   // 1/cs_k
__device__ float g_diff;

// ---------------------------------------------------------------------------
// K0: zero g_diff + precompute negated half-norms
// ---------------------------------------------------------------------------
__global__ void vq_prep(const float* __restrict__ emb) {
    int k = threadIdx.x;  // 512
    if (k == 0) g_diff = 0.f;
    float s = 0.f;
    #pragma unroll 8
    for (int c = 0; c < NC; c++) {
        float v = emb[c*NK + k];
        s = fmaf(v, v, s);
    }
    g_neghn[k] = -0.5f*s;
}

// ---------------------------------------------------------------------------
// K1: fused argmin (packed f32x2 FMA) + quantize gather + diff + scatter stats
//     Persistent: 148 blocks x 256 threads, one thread == one point per tile.
// ---------------------------------------------------------------------------
__global__ __launch_bounds__(TPB, 1) void vq_fused(
    const float* __restrict__ input, const float* __restrict__ emb,
    float* __restrict__ out, float* __restrict__ ind_out)
{
    extern __shared__ float sm[];
    float* acc  = sm;                          // [NC][KPAD]
    float* cnt  = sm + NC*KPAD;                // [NK]
    float* e_sm = sm + NC*KPAD + NK;           // [NC][ROWS]  (transposed: [c][k])
    float* nhn  = e_sm + NC*ROWS;              // [KC]
    float* red  = nhn + KC;                    // [TPB/32]

    const int tid = threadIdx.x;

    for (int i = tid; i < NC*KPAD + NK; i += TPB) sm[i] = 0.f;
    // (zeroing is ordered before first atomic use by the staging __syncthreads)

    float ddiff = 0.f;

    for (int t = blockIdx.x; t < NTILES; t += gridDim.x) {
        int n  = t*TPB + tid;
        int b  = n >> 12;
        int hw = n & 4095;
        const float* xp = input + b*NC*NHW + hw;

        float x[NC];
        #pragma unroll
        for (int c = 0; c < NC; c++) x[c] = xp[c*NHW];   // coalesced

        float best = -CUDART_INF_F;
        int bestk = 0;

        for (int k0 = 0; k0 < NK; k0 += KC) {
            __syncthreads();
            // Stage transposed chunk: e_sm[c][k] = emb[c][k0+k], float4 wide
            for (int i = tid; i < NC*KC/4; i += TPB) {
                int c  = i >> 6;
                int k4 = (i & 63)*4;
                float4 v = *(const float4*)&emb[c*NK + k0 + k4];
                *(float4*)&e_sm[c*ROWS + k4] = v;
            }
            nhn[tid] = g_neghn[k0 + tid];   // KC == TPB
            __syncthreads();

            for (int k = 0; k < KC; k += 16) {
                // 8 packed accumulators = 16 codes; init with -0.5||e||^2 pairs
                unsigned long long a[8];
                #pragma unroll
                for (int j = 0; j < 8; j++)
                    a[j] = *(const unsigned long long*)&nhn[k + 2*j];

                #pragma unroll
                for (int c = 0; c < NC; c++) {
                    unsigned long long xx;
                    asm("mov.b64 %0, {%1, %1};" : "=l"(xx) : "f"(x[c]));
                    const ulonglong2* ep =
                        (const ulonglong2*)&e_sm[c*ROWS + k];   // 16B aligned
                    ulonglong2 e01 = ep[0];   // codes k..k+3
                    ulonglong2 e23 = ep[1];   // codes k+4..k+7
                    ulonglong2 e45 = ep[2];
                    ulonglong2 e67 = ep[3];
                    asm("fma.rn.f32x2 %0, %1, %2, %0;" : "+l"(a[0]) : "l"(xx), "l"(e01.x));
                    asm("fma.rn.f32x2 %0, %1, %2, %0;" : "+l"(a[1]) : "l"(xx), "l"(e01.y));
                    asm("fma.rn.f32x2 %0, %1, %2, %0;" : "+l"(a[2]) : "l"(xx), "l"(e23.x));
                    asm("fma.rn.f32x2 %0, %1, %2, %0;" : "+l"(a[3]) : "l"(xx), "l"(e23.y));
                    asm("fma.rn.f32x2 %0, %1, %2, %0;" : "+l"(a[4]) : "l"(xx), "l"(e45.x));
                    asm("fma.rn.f32x2 %0, %1, %2, %0;" : "+l"(a[5]) : "l"(xx), "l"(e45.y));
                    asm("fma.rn.f32x2 %0, %1, %2, %0;" : "+l"(a[6]) : "l"(xx), "l"(e67.x));
                    asm("fma.rn.f32x2 %0, %1, %2, %0;" : "+l"(a[7]) : "l"(xx), "l"(e67.y));
                }

                #pragma unroll
                for (int j = 0; j < 8; j++) {
                    float lo, hi;
                    asm("mov.b64 {%0, %1}, %2;" : "=f"(lo), "=f"(hi) : "l"(a[j]));
                    // strict > keeps earliest index on ties (matches argmin)
                    if (lo > best) { best = lo; bestk = k0 + k + 2*j; }
                    if (hi > best) { best = hi; bestk = k0 + k + 2*j + 1; }
                }
            }
        }

        ind_out[n] = (float)bestk;

        // Gather chosen code, write NCHW out, diff partial, scatter stats.
        float* op = out + b*NC*NHW + hw;
        atomicAdd(&cnt[bestk], 1.f);
        #pragma unroll
        for (int c = 0; c < NC; c++) {
            float q = __ldg(&emb[c*NK + bestk]);
            op[c*NHW] = q;
            float d = q - x[c];
            ddiff = fmaf(d, d, ddiff);
            atomicAdd(&acc[c*KPAD + bestk], x[c]);
        }
    }

    // Commitment-loss block reduction (once per block)
    #pragma unroll
    for (int o = 16; o; o >>= 1) ddiff += __shfl_down_sync(0xffffffffu, ddiff, o);
    if ((tid & 31) == 0) red[tid >> 5] = ddiff;
    __syncthreads();
    if (tid == 0) {
        float s = 0.f;
        #pragma unroll
        for (int w = 0; w < TPB/32; w++) s += red[w];
        atomicAdd(&g_diff, s);
    }
    __syncthreads();

    // Flush per-block partials (plain coalesced stores, no global atomics)
    for (int i = tid; i < NC*NK; i += TPB)
        g_part[blockIdx.x*(NC*NK) + i] = acc[(i >> 9)*KPAD + (i & 511)];
    for (int i = tid; i < NK; i += TPB)
        g_pcnt[blockIdx.x*NK + i] = cnt[i];
}

// ---------------------------------------------------------------------------
// K2: reduce count partials, EMA cluster_size, normalizer inverses, diff
// ---------------------------------------------------------------------------
__global__ void vq_csum(const float* __restrict__ cs, float* __restrict__ d_out) {
    __shared__ float red[16];
    int k = threadIdx.x;  // 512
    float s = 0.f;
    #pragma unroll 4
    for (int b = 0; b < GRID; b++) s += g_pcnt[b*NK + k];
    float ncs = fmaf(cs[k], 0.99f, 0.01f*s);
    d_out[OFF_CS + k] = ncs;

    float v = ncs;
    #pragma unroll
    for (int o = 16; o; o >>= 1) v += __shfl_down_sync(0xffffffffu, v, o);
    if ((k & 31) == 0) red[k >> 5] = v;
    __syncthreads();
    if (k < 32) {
        float w = (k < 16) ? red[k] : 0.f;
        #pragma unroll
        for (int o = 8; o; o >>= 1) w += __shfl_down_sync(0xffffffffu, w, o);
        if (k == 0) red[0] = w;
    }
    __syncthreads();
    float tot = red[0];
    float csk = (ncs + 1e-5f) / (tot + 512.f*1e-5f) * tot;
    g_inv[k] = 1.f/csk;

    if (k == 0) d_out[OFF_DIFF] = g_diff * (1.f/(float)(NPTS*NC));
}

// ---------------------------------------------------------------------------
// K3: reduce embedding-sum partials + EMA + normalize (grid-wide)
// ---------------------------------------------------------------------------
__global__ void vq_ema(const float* __restrict__ eavg, float* __restrict__ d_out) {
    int i = blockIdx.x*blockDim.x + threadIdx.x;   // 32768 threads, 1 elem each
    float s = 0.f;
    #pragma unroll 4
    for (int b = 0; b < GRID; b++) s += g_part[b*(NC*NK) + i];
    float na = fmaf(eavg[i], 0.99f, 0.01f*s);
    d_out[OFF_EAVG + i] = na;
    d_out[OFF_EMB  + i] = na * g_inv[i & 511];
}

// ---------------------------------------------------------------------------
extern "C" void kernel_launch(void* const* d_in, const int* in_sizes, int n_in,
                              void* d_out, int out_size) {
    const float* input = (const float*)d_in[0];  // [B,C,H,W]
    const float* emb   = (const float*)d_in[1];  // [C,K]
    const float* cs    = (const float*)d_in[2];  // [K]
    const float* eavg  = (const float*)d_in[3];  // [C,K]
    float* out = (float*)d_out;

    const int fused_smem = (NC*KPAD + NK + NC*ROWS + KC + TPB/32)*(int)sizeof(float);
    cudaFuncSetAttribute(vq_fused, cudaFuncAttributeMaxDynamicSharedMemorySize,
                         fused_smem);

    vq_prep<<<1, NK>>>(emb);
    vq_fused<<<GRID, TPB, fused_smem>>>(input, emb, out + OFF_OUT, out + OFF_IND);
    vq_csum<<<1, NK>>>(cs, out);
    vq_ema<<<NC*NK/TPB, TPB>>>(eavg, out);
}

// round 4
// speedup vs baseline: 1.3651x; 1.1657x over previous
#include <cuda_runtime.h>
#include <math_constants.h>

// Problem dims
#define NB 64
#define NC 64
#define NH 64
#define NW 64
#define NK 512
#define NHW (NH*NW)          // 4096
#define NPTS (NB*NHW)        // 262144

#define MP   128             // points per tile
#define KC   128             // codes per chunk
#define NCHUNK (NK/KC)       // 4
#define NTILES (NPTS/MP)     // 2048

// Output packing (flattened reference tuple, all float32)
#define OFF_OUT  0
#define OFF_DIFF (NPTS*NC)
#define OFF_IND  (OFF_DIFF + 1)
#define OFF_EMB  (OFF_IND + NPTS)
#define OFF_CS   (OFF_EMB + NC*NK)
#define OFF_EAVG (OFF_CS + NK)

#define GRID 148
#define TPB  256
#define XPAD 132             // xs row stride (floats), 528B (16B aligned)
#define EPAD 132             // e_sm row stride
#define KPAD 513             // accumulator row pad

// Scratch (__device__ globals; no allocation allowed)
__device__ float g_neghn[NK];      // -0.5*||e_k||^2
__device__ float g_esum[NC*NK];    // global embedding-sum accumulator
__device__ float g_counts[NK];
__device__ float g_inv[NK];        // 1/cs_k
__device__ float g_diff;

// ---------------------------------------------------------------------------
// K0: zero global accumulators + precompute negated half-norms
// ---------------------------------------------------------------------------
__global__ void vq_prep(const float* __restrict__ emb) {
    int gt = blockIdx.x*blockDim.x + threadIdx.x;   // 64 x 512
    if (gt < NC*NK) g_esum[gt] = 0.f;
    if (blockIdx.x == 0) {
        int k = threadIdx.x;
        g_counts[k] = 0.f;
        if (k == 0) g_diff = 0.f;
        float s = 0.f;
        #pragma unroll 8
        for (int c = 0; c < NC; c++) {
            float v = emb[c*NK + k];
            s = fmaf(v, v, s);
        }
        g_neghn[k] = -0.5f*s;
    }
}

// ---------------------------------------------------------------------------
// K1: fused register-blocked score GEMM + argmax + gather + diff + scatter
//     Persistent 148 blocks x 256 threads. Tile = 128 points.
//     Thread tile = 8 points x 8 codes with packed f32x2 accumulators.
// ---------------------------------------------------------------------------
__global__ __launch_bounds__(TPB, 1) void vq_fused(
    const float* __restrict__ input, const float* __restrict__ emb,
    float* __restrict__ out, float* __restrict__ ind_out)
{
    extern __shared__ float sm[];
    float* acc  = sm;                       // [NC][KPAD]   32832
    float* cnt  = acc + NC*KPAD;            // [NK]         512
    float* xs   = cnt + NK;                 // [NC][XPAD]   8448
    float* e_sm = xs + NC*XPAD;             // [NC][EPAD]   8448  (union: sred)
    float* nhn  = e_sm + NC*EPAD;           // [NK]         512
    float* skf  = nhn + NK;                 // [MP]         128
    float* red  = skf + MP;                 // [8]
    int*   sk   = (int*)skf;

    const int tid = threadIdx.x;
    const int px  = tid & 15;               // point group
    const int ky  = tid >> 4;               // code group
    const int p0  = px*8;
    const int k0  = ky*8;

    for (int i = tid; i < NC*KPAD + NK; i += TPB) sm[i] = 0.f;   // acc + cnt
    for (int i = tid; i < NK; i += TPB) nhn[i] = g_neghn[i];
    // (ordered before first use by the per-tile __syncthreads below)

    float ddiff = 0.f;

    for (int t = blockIdx.x; t < NTILES; t += gridDim.x) {
        const int n0  = t*MP;
        const int b   = n0 >> 12;
        const int hw0 = n0 & 4095;
        const float* xin = input + (size_t)b*NC*NHW + hw0;
        float*       op  = out   + (size_t)b*NC*NHW + hw0;

        __syncthreads();   // prior tile done reading xs / e_sm(sred)

        // Stage x-tile: xs[c][p] (coalesced float4)
        for (int i = tid; i < NC*(MP/4); i += TPB) {
            int c  = i >> 5;
            int p4 = (i & 31)*4;
            *(float4*)&xs[c*XPAD + p4] = *(const float4*)&xin[c*NHW + p4];
        }

        float best[8];
        int   bi[8];
        #pragma unroll
        for (int pp = 0; pp < 8; pp++) { best[pp] = -CUDART_INF_F; bi[pp] = 0; }

        for (int ch = 0; ch < NCHUNK; ch++) {
            const int kc0 = ch*KC;
            if (ch) __syncthreads();     // prior chunk done reading e_sm
            for (int i = tid; i < NC*(KC/4); i += TPB) {
                int c  = i >> 5;
                int k4 = (i & 31)*4;
                *(float4*)&e_sm[c*EPAD + k4] =
                    *(const float4*)&emb[c*NK + kc0 + k4];
            }
            __syncthreads();

            // init packed accumulators with -0.5||e||^2 pairs
            unsigned long long a[8][4];
            {
                ulonglong2 i01 = *(const ulonglong2*)&nhn[kc0 + k0];
                ulonglong2 i23 = *(const ulonglong2*)&nhn[kc0 + k0 + 4];
                #pragma unroll
                for (int pp = 0; pp < 8; pp++) {
                    a[pp][0] = i01.x; a[pp][1] = i01.y;
                    a[pp][2] = i23.x; a[pp][3] = i23.y;
                }
            }

            #pragma unroll 4
            for (int c = 0; c < NC; c++) {
                float4 xa = *(const float4*)&xs[c*XPAD + p0];
                float4 xb = *(const float4*)&xs[c*XPAD + p0 + 4];
                ulonglong2 ev = *(const ulonglong2*)&e_sm[c*EPAD + k0];
                ulonglong2 ew = *(const ulonglong2*)&e_sm[c*EPAD + k0 + 4];
                unsigned long long xx[8];
                asm("mov.b64 %0, {%1, %1};" : "=l"(xx[0]) : "f"(xa.x));
                asm("mov.b64 %0, {%1, %1};" : "=l"(xx[1]) : "f"(xa.y));
                asm("mov.b64 %0, {%1, %1};" : "=l"(xx[2]) : "f"(xa.z));
                asm("mov.b64 %0, {%1, %1};" : "=l"(xx[3]) : "f"(xa.w));
                asm("mov.b64 %0, {%1, %1};" : "=l"(xx[4]) : "f"(xb.x));
                asm("mov.b64 %0, {%1, %1};" : "=l"(xx[5]) : "f"(xb.y));
                asm("mov.b64 %0, {%1, %1};" : "=l"(xx[6]) : "f"(xb.z));
                asm("mov.b64 %0, {%1, %1};" : "=l"(xx[7]) : "f"(xb.w));
                #pragma unroll
                for (int pp = 0; pp < 8; pp++) {
                    asm("fma.rn.f32x2 %0, %1, %2, %0;" : "+l"(a[pp][0]) : "l"(xx[pp]), "l"(ev.x));
                    asm("fma.rn.f32x2 %0, %1, %2, %0;" : "+l"(a[pp][1]) : "l"(xx[pp]), "l"(ev.y));
                    asm("fma.rn.f32x2 %0, %1, %2, %0;" : "+l"(a[pp][2]) : "l"(xx[pp]), "l"(ew.x));
                    asm("fma.rn.f32x2 %0, %1, %2, %0;" : "+l"(a[pp][3]) : "l"(xx[pp]), "l"(ew.y));
                }
            }

            // per-thread argmax update (ascending code order within thread)
            #pragma unroll
            for (int pp = 0; pp < 8; pp++) {
                #pragma unroll
                for (int j = 0; j < 4; j++) {
                    float lo, hi;
                    asm("mov.b64 {%0, %1}, %2;" : "=f"(lo), "=f"(hi) : "l"(a[pp][j]));
                    int code = kc0 + k0 + 2*j;
                    if (lo > best[pp]) { best[pp] = lo; bi[pp] = code; }
                    if (hi > best[pp]) { best[pp] = hi; bi[pp] = code + 1; }
                }
            }
        }

        // Cross-thread reduction per point (16 candidates each), reusing e_sm
        __syncthreads();
        float* sbest = e_sm;            // [MP][16]
        float* sidx  = e_sm + MP*16;    // [MP][16]
        #pragma unroll
        for (int pp = 0; pp < 8; pp++) {
            int p = p0 + pp;
            sbest[p*16 + ky] = best[pp];
            sidx [p*16 + ky] = (float)bi[pp];
        }
        __syncthreads();
        if (tid < MP) {
            float bb = -CUDART_INF_F;
            int   bk = NK;
            #pragma unroll
            for (int g = 0; g < 16; g++) {
                float v  = sbest[tid*16 + g];
                int   id = (int)sidx[tid*16 + g];
                if (v > bb || (v == bb && id < bk)) { bb = v; bk = id; }
            }
            sk[tid] = bk;
            ind_out[n0 + tid] = (float)bk;
            atomicAdd(&cnt[bk], 1.f);
        }
        __syncthreads();

        // Gather chosen codes -> out, diff partials, scatter x into acc
        for (int i = tid; i < NC*MP; i += TPB) {
            int c = i >> 7;
            int p = i & (MP-1);
            int k = sk[p];
            float xv = xs[c*XPAD + p];
            float q  = __ldg(&emb[c*NK + k]);
            op[c*NHW + p] = q;
            float d = q - xv;
            ddiff = fmaf(d, d, ddiff);
            atomicAdd(&acc[c*KPAD + k], xv);
        }
    }

    // Commitment-loss reduction
    #pragma unroll
    for (int o = 16; o; o >>= 1) ddiff += __shfl_down_sync(0xffffffffu, ddiff, o);
    if ((tid & 31) == 0) red[tid >> 5] = ddiff;
    __syncthreads();
    if (tid == 0) {
        float s = 0.f;
        #pragma unroll
        for (int w = 0; w < TPB/32; w++) s += red[w];
        atomicAdd(&g_diff, s);
    }

    // Flush smem stats straight into global accumulators (REDG, no-return)
    for (int i = tid; i < NC*NK; i += TPB)
        atomicAdd(&g_esum[i], acc[(i >> 9)*KPAD + (i & 511)]);
    for (int i = tid; i < NK; i += TPB)
        atomicAdd(&g_counts[i], cnt[i]);
}

// ---------------------------------------------------------------------------
// K2: EMA cluster_size, normalizer inverses, diff
// ---------------------------------------------------------------------------
__global__ void vq_csum(const float* __restrict__ cs, float* __restrict__ d_out) {
    __shared__ float red[16];
    int k = threadIdx.x;  // 512
    float ncs = fmaf(cs[k], 0.99f, 0.01f*g_counts[k]);
    d_out[OFF_CS + k] = ncs;

    float v = ncs;
    #pragma unroll
    for (int o = 16; o; o >>= 1) v += __shfl_down_sync(0xffffffffu, v, o);
    if ((k & 31) == 0) red[k >> 5] = v;
    __syncthreads();
    if (k < 32) {
        float w = (k < 16) ? red[k] : 0.f;
        #pragma unroll
        for (int o = 8; o; o >>= 1) w += __shfl_down_sync(0xffffffffu, w, o);
        if (k == 0) red[0] = w;
    }
    __syncthreads();
    float tot = red[0];
    float csk = (ncs + 1e-5f) / (tot + 512.f*1e-5f) * tot;
    g_inv[k] = 1.f/csk;

    if (k == 0) d_out[OFF_DIFF] = g_diff * (1.f/(float)(NPTS*NC));
}

// ---------------------------------------------------------------------------
// K3: EMA embedding_avg + normalized embedding
// ---------------------------------------------------------------------------
__global__ void vq_ema(const float* __restrict__ eavg, float* __restrict__ d_out) {
    int i = blockIdx.x*blockDim.x + threadIdx.x;   // 32768 threads
    float na = fmaf(eavg[i], 0.99f, 0.01f*g_esum[i]);
    d_out[OFF_EAVG + i] = na;
    d_out[OFF_EMB  + i] = na * g_inv[i & 511];
}

// ---------------------------------------------------------------------------
extern "C" void kernel_launch(void* const* d_in, const int* in_sizes, int n_in,
                              void* d_out, int out_size) {
    const float* input = (const float*)d_in[0];  // [B,C,H,W]
    const float* emb   = (const float*)d_in[1];  // [C,K]
    const float* cs    = (const float*)d_in[2];  // [K]
    const float* eavg  = (const float*)d_in[3];  // [C,K]
    float* out = (float*)d_out;

    const int fused_smem =
        (NC*KPAD + NK + NC*XPAD + NC*EPAD + NK + MP + 8)*(int)sizeof(float);
    cudaFuncSetAttribute(vq_fused, cudaFuncAttributeMaxDynamicSharedMemorySize,
                         fused_smem);

    vq_prep<<<64, 512>>>(emb);
    vq_fused<<<GRID, TPB, fused_smem>>>(input, emb, out + OFF_OUT, out + OFF_IND);
    vq_csum<<<1, NK>>>(cs, out);
    vq_ema<<<NC*NK/TPB, TPB>>>(eavg, out);
}

// round 5
// speedup vs baseline: 1.3866x; 1.0157x over previous
#include <cuda_runtime.h>
#include <math_constants.h>

// Problem dims
#define NB 64
#define NC 64
#define NH 64
#define NW 64
#define NK 512
#define NHW (NH*NW)          // 4096
#define NPTS (NB*NHW)        // 262144

#define MP   128             // points per tile
#define KC   128             // codes per chunk
#define NCHUNK (NK/KC)       // 4
#define NTILES (NPTS/MP)     // 2048

// Output packing (flattened reference tuple, all float32)
#define OFF_OUT  0
#define OFF_DIFF (NPTS*NC)
#define OFF_IND  (OFF_DIFF + 1)
#define OFF_EMB  (OFF_IND + NPTS)
#define OFF_CS   (OFF_EMB + NC*NK)
#define OFF_EAVG (OFF_CS + NK)

#define GRID 148
#define TPB  256
#define XPAD 132             // xs row stride (floats), 528B (16B aligned)
#define EPAD 132             // e_sm row stride
#define KPAD 513             // accumulator row pad

// Scratch (__device__ globals; no allocation allowed)
__device__ float g_neghn[NK];      // -0.5*||e_k||^2
__device__ float g_esum[NC*NK];    // global embedding-sum accumulator
__device__ float g_counts[NK];
__device__ float g_inv[NK];        // 1/cs_k
__device__ float g_diff;

// ---------------------------------------------------------------------------
// K0: zero global accumulators + precompute negated half-norms
// ---------------------------------------------------------------------------
__global__ void vq_prep(const float* __restrict__ emb) {
    int gt = blockIdx.x*blockDim.x + threadIdx.x;   // 64 x 512
    if (gt < NC*NK) g_esum[gt] = 0.f;
    if (blockIdx.x == 0) {
        int k = threadIdx.x;
        g_counts[k] = 0.f;
        if (k == 0) g_diff = 0.f;
        float s = 0.f;
        #pragma unroll 8
        for (int c = 0; c < NC; c++) {
            float v = emb[c*NK + k];
            s = fmaf(v, v, s);
        }
        g_neghn[k] = -0.5f*s;
    }
}

// ---------------------------------------------------------------------------
// K1: fused register-blocked score GEMM + argmax + gather + diff + scatter
//     Persistent 148 blocks x 256 threads. Tile = 128 points.
//     Thread tile = (4+4 points) x (4+4 codes), packed f32x2 accumulators.
//     The 4+4 split gives every LDS.128 a 16B lane stride -> conflict-free.
// ---------------------------------------------------------------------------
__global__ __launch_bounds__(TPB, 1) void vq_fused(
    const float* __restrict__ input, const float* __restrict__ emb,
    float* __restrict__ out, float* __restrict__ ind_out)
{
    extern __shared__ float sm[];
    float* acc  = sm;                       // [NC][KPAD]   32832
    float* cnt  = acc + NC*KPAD;            // [NK]         512
    float* xs   = cnt + NK;                 // [NC][XPAD]   8448
    float* e_sm = xs + NC*XPAD;             // [NC][EPAD]   8448  (union: sred)
    float* nhn  = e_sm + NC*EPAD;           // [NK]         512
    float* skf  = nhn + NK;                 // [MP]         128
    float* red  = skf + MP;                 // [8]
    int*   sk   = (int*)skf;

    const int tid = threadIdx.x;
    const int px  = tid & 15;               // point group
    const int ky  = tid >> 4;               // code group
    const int p0a = px*4;                   // points p0a..p0a+3
    const int p0b = 64 + px*4;              // points p0b..p0b+3
    const int k0a = ky*4;                   // codes  k0a..k0a+3 (within chunk)
    const int k0b = 64 + ky*4;              // codes  k0b..k0b+3

    for (int i = tid; i < NC*KPAD + NK; i += TPB) sm[i] = 0.f;   // acc + cnt
    for (int i = tid; i < NK; i += TPB) nhn[i] = g_neghn[i];
    // (ordered before first use by the per-tile __syncthreads below)

    float ddiff = 0.f;

    for (int t = blockIdx.x; t < NTILES; t += gridDim.x) {
        const int n0  = t*MP;
        const int b   = n0 >> 12;
        const int hw0 = n0 & 4095;
        const float* xin = input + (size_t)b*NC*NHW + hw0;
        float*       op  = out   + (size_t)b*NC*NHW + hw0;

        __syncthreads();   // prior tile done reading xs / e_sm(sred)

        // Stage x-tile: xs[c][p] (coalesced float4)
        for (int i = tid; i < NC*(MP/4); i += TPB) {
            int c  = i >> 5;
            int p4 = (i & 31)*4;
            *(float4*)&xs[c*XPAD + p4] = *(const float4*)&xin[c*NHW + p4];
        }

        float best[8];
        int   bi[8];
        #pragma unroll
        for (int pp = 0; pp < 8; pp++) { best[pp] = -CUDART_INF_F; bi[pp] = 0; }

        for (int ch = 0; ch < NCHUNK; ch++) {
            const int kc0 = ch*KC;
            if (ch) __syncthreads();     // prior chunk done reading e_sm
            for (int i = tid; i < NC*(KC/4); i += TPB) {
                int c  = i >> 5;
                int k4 = (i & 31)*4;
                *(float4*)&e_sm[c*EPAD + k4] =
                    *(const float4*)&emb[c*NK + kc0 + k4];
            }
            __syncthreads();

            // init packed accumulators with -0.5||e||^2 pairs
            // a[pp][0]: codes k0a+0,1  a[pp][1]: k0a+2,3
            // a[pp][2]: codes k0b+0,1  a[pp][3]: k0b+2,3
            unsigned long long a[8][4];
            {
                ulonglong2 ia = *(const ulonglong2*)&nhn[kc0 + k0a];
                ulonglong2 ib = *(const ulonglong2*)&nhn[kc0 + k0b];
                #pragma unroll
                for (int pp = 0; pp < 8; pp++) {
                    a[pp][0] = ia.x; a[pp][1] = ia.y;
                    a[pp][2] = ib.x; a[pp][3] = ib.y;
                }
            }

            #pragma unroll 4
            for (int c = 0; c < NC; c++) {
                float4 xa = *(const float4*)&xs[c*XPAD + p0a];   // 16B lane stride
                float4 xb = *(const float4*)&xs[c*XPAD + p0b];
                ulonglong2 ev = *(const ulonglong2*)&e_sm[c*EPAD + k0a]; // bcast
                ulonglong2 ew = *(const ulonglong2*)&e_sm[c*EPAD + k0b];
                unsigned long long xx[8];
                asm("mov.b64 %0, {%1, %1};" : "=l"(xx[0]) : "f"(xa.x));
                asm("mov.b64 %0, {%1, %1};" : "=l"(xx[1]) : "f"(xa.y));
                asm("mov.b64 %0, {%1, %1};" : "=l"(xx[2]) : "f"(xa.z));
                asm("mov.b64 %0, {%1, %1};" : "=l"(xx[3]) : "f"(xa.w));
                asm("mov.b64 %0, {%1, %1};" : "=l"(xx[4]) : "f"(xb.x));
                asm("mov.b64 %0, {%1, %1};" : "=l"(xx[5]) : "f"(xb.y));
                asm("mov.b64 %0, {%1, %1};" : "=l"(xx[6]) : "f"(xb.z));
                asm("mov.b64 %0, {%1, %1};" : "=l"(xx[7]) : "f"(xb.w));
                #pragma unroll
                for (int pp = 0; pp < 8; pp++) {
                    asm("fma.rn.f32x2 %0, %1, %2, %0;" : "+l"(a[pp][0]) : "l"(xx[pp]), "l"(ev.x));
                    asm("fma.rn.f32x2 %0, %1, %2, %0;" : "+l"(a[pp][1]) : "l"(xx[pp]), "l"(ev.y));
                    asm("fma.rn.f32x2 %0, %1, %2, %0;" : "+l"(a[pp][2]) : "l"(xx[pp]), "l"(ew.x));
                    asm("fma.rn.f32x2 %0, %1, %2, %0;" : "+l"(a[pp][3]) : "l"(xx[pp]), "l"(ew.y));
                }
            }

            // per-thread argmax update (ascending code order within thread)
            #pragma unroll
            for (int pp = 0; pp < 8; pp++) {
                #pragma unroll
                for (int j = 0; j < 4; j++) {
                    float lo, hi;
                    asm("mov.b64 {%0, %1}, %2;" : "=f"(lo), "=f"(hi) : "l"(a[pp][j]));
                    int code = kc0 + ((j < 2) ? k0a : k0b) + 2*(j & 1);
                    if (lo > best[pp]) { best[pp] = lo; bi[pp] = code; }
                    if (hi > best[pp]) { best[pp] = hi; bi[pp] = code + 1; }
                }
            }
        }

        // Cross-thread reduction per point (16 candidates each), reusing e_sm
        __syncthreads();
        float* sbest = e_sm;            // [MP][16]
        float* sidx  = e_sm + MP*16;    // [MP][16]
        #pragma unroll
        for (int pp = 0; pp < 8; pp++) {
            int p = (pp < 4) ? (p0a + pp) : (p0b + pp - 4);
            sbest[p*16 + ky] = best[pp];
            sidx [p*16 + ky] = (float)bi[pp];
        }
        __syncthreads();
        if (tid < MP) {
            float bb = -CUDART_INF_F;
            int   bk = NK;
            #pragma unroll
            for (int g = 0; g < 16; g++) {
                float v  = sbest[tid*16 + g];
                int   id = (int)sidx[tid*16 + g];
                if (v > bb || (v == bb && id < bk)) { bb = v; bk = id; }
            }
            sk[tid] = bk;
            ind_out[n0 + tid] = (float)bk;
            atomicAdd(&cnt[bk], 1.f);
        }
        __syncthreads();

        // Gather chosen codes -> out, diff partials, scatter x into acc
        for (int i = tid; i < NC*MP; i += TPB) {
            int c = i >> 7;
            int p = i & (MP-1);
            int k = sk[p];
            float xv = xs[c*XPAD + p];
            float q  = __ldg(&emb[c*NK + k]);
            op[c*NHW + p] = q;
            float d = q - xv;
            ddiff = fmaf(d, d, ddiff);
            atomicAdd(&acc[c*KPAD + k], xv);
        }
    }

    // Commitment-loss reduction
    #pragma unroll
    for (int o = 16; o; o >>= 1) ddiff += __shfl_down_sync(0xffffffffu, ddiff, o);
    if ((tid & 31) == 0) red[tid >> 5] = ddiff;
    __syncthreads();
    if (tid == 0) {
        float s = 0.f;
        #pragma unroll
        for (int w = 0; w < TPB/32; w++) s += red[w];
        atomicAdd(&g_diff, s);
    }

    // Flush smem stats straight into global accumulators (REDG, no-return)
    for (int i = tid; i < NC*NK; i += TPB)
        atomicAdd(&g_esum[i], acc[(i >> 9)*KPAD + (i & 511)]);
    for (int i = tid; i < NK; i += TPB)
        atomicAdd(&g_counts[i], cnt[i]);
}

// ---------------------------------------------------------------------------
// K2: EMA cluster_size, normalizer inverses, diff
// ---------------------------------------------------------------------------
__global__ void vq_csum(const float* __restrict__ cs, float* __restrict__ d_out) {
    __shared__ float red[16];
    int k = threadIdx.x;  // 512
    float ncs = fmaf(cs[k], 0.99f, 0.01f*g_counts[k]);
    d_out[OFF_CS + k] = ncs;

    float v = ncs;
    #pragma unroll
    for (int o = 16; o; o >>= 1) v += __shfl_down_sync(0xffffffffu, v, o);
    if ((k & 31) == 0) red[k >> 5] = v;
    __syncthreads();
    if (k < 32) {
        float w = (k < 16) ? red[k] : 0.f;
        #pragma unroll
        for (int o = 8; o; o >>= 1) w += __shfl_down_sync(0xffffffffu, w, o);
        if (k == 0) red[0] = w;
    }
    __syncthreads();
    float tot = red[0];
    float csk = (ncs + 1e-5f) / (tot + 512.f*1e-5f) * tot;
    g_inv[k] = 1.f/csk;

    if (k == 0) d_out[OFF_DIFF] = g_diff * (1.f/(float)(NPTS*NC));
}

// ---------------------------------------------------------------------------
// K3: EMA embedding_avg + normalized embedding
// ---------------------------------------------------------------------------
__global__ void vq_ema(const float* __restrict__ eavg, float* __restrict__ d_out) {
    int i = blockIdx.x*blockDim.x + threadIdx.x;   // 32768 threads
    float na = fmaf(eavg[i], 0.99f, 0.01f*g_esum[i]);
    d_out[OFF_EAVG + i] = na;
    d_out[OFF_EMB  + i] = na * g_inv[i & 511];
}

// ---------------------------------------------------------------------------
extern "C" void kernel_launch(void* const* d_in, const int* in_sizes, int n_in,
                              void* d_out, int out_size) {
    const float* input = (const float*)d_in[0];  // [B,C,H,W]
    const float* emb   = (const float*)d_in[1];  // [C,K]
    const float* cs    = (const float*)d_in[2];  // [K]
    const float* eavg  = (const float*)d_in[3];  // [C,K]
    float* out = (float*)d_out;

    const int fused_smem =
        (NC*KPAD + NK + NC*XPAD + NC*EPAD + NK + MP + 8)*(int)sizeof(float);
    cudaFuncSetAttribute(vq_fused, cudaFuncAttributeMaxDynamicSharedMemorySize,
                         fused_smem);

    vq_prep<<<64, 512>>>(emb);
    vq_fused<<<GRID, TPB, fused_smem>>>(input, emb, out + OFF_OUT, out + OFF_IND);
    vq_csum<<<1, NK>>>(cs, out);
    vq_ema<<<NC*NK/TPB, TPB>>>(eavg, out);
}

// round 8
// speedup vs baseline: 1.9051x; 1.3740x over previous
#include <cuda_runtime.h>
#include <cuda_bf16.h>
#include <math_constants.h>
#include <cstdint>

#define NB 64
#define NC 64
#define NHW 4096
#define NPTS 262144
#define NK 512
#define MP 128
#define NTILES (NPTS/MP)
#define GRID 148
#define TPB 256

#define OFF_OUT  0
#define OFF_DIFF (NPTS*NC)
#define OFF_IND  (OFF_DIFF + 1)
#define OFF_EMB  (OFF_IND + NPTS)
#define OFF_CS   (OFF_EMB + NC*NK)
#define OFF_EAVG (OFF_CS + NK)

// row pitches (bytes): 64 bf16 data + 16B pad -> 36 banks -> conflict-free frags
#define ERB 144
#define XRB 144

// smem offsets (bytes)
#define A_EH   0                    // 512*144 = 73728
#define A_EL   73728
#define A_XH   147456               // 128*144 = 18432
#define A_XL   165888
#define A_NHN  184320               // 512*4
#define A_NRM2 186368               // 256*4
#define A_NORM 187392               // 128*4
#define A_SK   187904               // 128*4
#define A_RED  188416               // 8*4
#define A_SMEM 188448

__device__ float g_neghn[NK];
__device__ float g_margc;
__device__ float g_esum[NC*NK];
__device__ float g_counts[NK];
__device__ float g_inv[NK];
__device__ float g_diff;
__device__ int   g_nsusp;
__device__ int   g_susp[NPTS];

__device__ __forceinline__ void mma_bf16(float* d, const uint32_t* a,
                                         uint32_t b0, uint32_t b1) {
    asm volatile(
        "mma.sync.aligned.m16n8k16.row.col.f32.bf16.bf16.f32 "
        "{%0,%1,%2,%3}, {%4,%5,%6,%7}, {%8,%9}, {%0,%1,%2,%3};"
        : "+f"(d[0]), "+f"(d[1]), "+f"(d[2]), "+f"(d[3])
        : "r"(a[0]), "r"(a[1]), "r"(a[2]), "r"(a[3]), "r"(b0), "r"(b1));
}

// ---------------------------------------------------------------------------
__global__ void vq_prep(const float* __restrict__ emb) {
    __shared__ float redm[16];
    int gt = blockIdx.x*blockDim.x + threadIdx.x;   // 64 x 512
    if (gt < NC*NK) g_esum[gt] = 0.f;
    if (blockIdx.x != 0) return;
    int k = threadIdx.x;
    g_counts[k] = 0.f;
    if (k == 0) { g_diff = 0.f; g_nsusp = 0; }
    float s = 0.f;
    #pragma unroll 8
    for (int c = 0; c < NC; c++) { float v = emb[c*NK + k]; s = fmaf(v, v, s); }
    g_neghn[k] = -0.5f*s;
    float m = s;
    #pragma unroll
    for (int o = 16; o; o >>= 1) m = fmaxf(m, __shfl_down_sync(0xffffffffu, m, o));
    if ((k & 31) == 0) redm[k >> 5] = m;
    __syncthreads();
    if (k == 0) {
        float mm = 0.f;
        #pragma unroll
        for (int w = 0; w < 16; w++) mm = fmaxf(mm, redm[w]);
        g_margc = (8.0f/65536.0f)*sqrtf(mm);
    }
}

// ---------------------------------------------------------------------------
// Scores via mma.sync bf16 hi/lo; certified argmax; gather/diff/scatter.
// ---------------------------------------------------------------------------
__global__ __launch_bounds__(TPB, 1) void vq_scores(
    const float* __restrict__ input, const float* __restrict__ emb,
    float* __restrict__ out, float* __restrict__ ind_out)
{
    extern __shared__ char sma[];
    float* nhn  = (float*)(sma + A_NHN);
    float* nrm2 = (float*)(sma + A_NRM2);
    float* norm = (float*)(sma + A_NORM);
    int*   sk   = (int*)  (sma + A_SK);
    float* red  = (float*)(sma + A_RED);

    const int tid = threadIdx.x;
    const int wid = tid >> 5;
    const int lid = tid & 31;
    const int gid = lid >> 2;     // group id 0..7
    const int tig = lid & 3;      // thread-in-group

    // Stage E hi/lo (rows = code k, 64 bf16 cols = c)
    for (int i = tid; i < NK*NC/4; i += TPB) {
        int c  = i >> 7;
        int k4 = (i & 127)*4;
        float4 v = *(const float4*)&emb[c*NK + k4];
        float vv[4] = {v.x, v.y, v.z, v.w};
        #pragma unroll
        for (int j = 0; j < 4; j++) {
            __nv_bfloat16 h = __float2bfloat16(vv[j]);
            __nv_bfloat16 l = __float2bfloat16(vv[j] - __bfloat162float(h));
            *(__nv_bfloat16*)(sma + A_EH + (k4 + j)*ERB + c*2) = h;
            *(__nv_bfloat16*)(sma + A_EL + (k4 + j)*ERB + c*2) = l;
        }
    }
    for (int i = tid; i < NK; i += TPB) nhn[i] = g_neghn[i];
    const float margc = g_margc;

    float ddiff = 0.f;

    for (int t = blockIdx.x; t < NTILES; t += gridDim.x) {
        const int n0tile = t*MP;
        const int b      = n0tile >> 12;
        const int hw0    = n0tile & 4095;
        const float* xin = input + (size_t)b*NC*NHW + hw0;
        float*       op  = out   + (size_t)b*NC*NHW + hw0;

        __syncthreads();   // prior tile fully consumed

        // stage X hi/lo (rows = point) + per-point norm partials
        {
            const int p = tid & 127;
            float nsum = 0.f;
            #pragma unroll 8
            for (int j = 0; j < 32; j++) {
                int c = (tid >> 7) + 2*j;
                float v = xin[c*NHW + p];
                __nv_bfloat16 h = __float2bfloat16(v);
                __nv_bfloat16 l = __float2bfloat16(v - __bfloat162float(h));
                *(__nv_bfloat16*)(sma + A_XH + p*XRB + c*2) = h;
                *(__nv_bfloat16*)(sma + A_XL + p*XRB + c*2) = l;
                nsum = fmaf(v, v, nsum);
            }
            nrm2[tid] = nsum;
        }
        __syncthreads();
        if (tid < MP) norm[tid] = nrm2[tid] + nrm2[tid + 128];
        __syncthreads();

        // Load A fragments for warp's 16 points (rows r0=wid*16+gid, r1=r0+8)
        const int r0 = wid*16 + gid;
        const int r1 = r0 + 8;
        uint32_t ah[4][4], al[4][4];
        #pragma unroll
        for (int ks = 0; ks < 4; ks++) {
            int c0 = (ks*16 + tig*2)*2;      // byte offset of k-cols tig*2
            ah[ks][0] = *(const uint32_t*)(sma + A_XH + r0*XRB + c0);
            ah[ks][1] = *(const uint32_t*)(sma + A_XH + r1*XRB + c0);
            ah[ks][2] = *(const uint32_t*)(sma + A_XH + r0*XRB + c0 + 16);
            ah[ks][3] = *(const uint32_t*)(sma + A_XH + r1*XRB + c0 + 16);
            al[ks][0] = *(const uint32_t*)(sma + A_XL + r0*XRB + c0);
            al[ks][1] = *(const uint32_t*)(sma + A_XL + r1*XRB + c0);
            al[ks][2] = *(const uint32_t*)(sma + A_XL + r0*XRB + c0 + 16);
            al[ks][3] = *(const uint32_t*)(sma + A_XL + r1*XRB + c0 + 16);
        }

        // per-lane best/2nd-best for its two rows
        float b1lo = -CUDART_INF_F, b2lo = -CUDART_INF_F;
        float b1hi = -CUDART_INF_F, b2hi = -CUDART_INF_F;
        int   i1lo = 0, i1hi = 0;

        #pragma unroll 1
        for (int ch = 0; ch < 8; ch++) {
            const int n0 = ch*64;
            float acc[8][4];
            #pragma unroll
            for (int nt = 0; nt < 8; nt++)
                acc[nt][0] = acc[nt][1] = acc[nt][2] = acc[nt][3] = 0.f;

            #pragma unroll
            for (int nt = 0; nt < 8; nt++) {
                const int n = n0 + nt*8 + gid;     // B col for this lane
                #pragma unroll
                for (int ks = 0; ks < 4; ks++) {
                    int kb = (ks*16 + tig*2)*2;
                    uint32_t bh0 = *(const uint32_t*)(sma + A_EH + n*ERB + kb);
                    uint32_t bh1 = *(const uint32_t*)(sma + A_EH + n*ERB + kb + 16);
                    uint32_t bl0 = *(const uint32_t*)(sma + A_EL + n*ERB + kb);
                    uint32_t bl1 = *(const uint32_t*)(sma + A_EL + n*ERB + kb + 16);
                    mma_bf16(acc[nt], ah[ks], bh0, bh1);   // xh*eh
                    mma_bf16(acc[nt], ah[ks], bl0, bl1);   // xh*el
                    mma_bf16(acc[nt], al[ks], bh0, bh1);   // xl*eh
                }
            }

            // argmax update (codes ascending within lane)
            #pragma unroll
            for (int nt = 0; nt < 8; nt++) {
                int code0 = n0 + nt*8 + tig*2;
                float nh0 = nhn[code0], nh1 = nhn[code0 + 1];
                float v0 = acc[nt][0] + nh0;   // (r0, code0)
                float v1 = acc[nt][1] + nh1;   // (r0, code0+1)
                float v2 = acc[nt][2] + nh0;   // (r1, code0)
                float v3 = acc[nt][3] + nh1;   // (r1, code0+1)
                if (v0 > b1lo) { b2lo = b1lo; b1lo = v0; i1lo = code0; }
                else           { b2lo = fmaxf(b2lo, v0); }
                if (v1 > b1lo) { b2lo = b1lo; b1lo = v1; i1lo = code0 + 1; }
                else           { b2lo = fmaxf(b2lo, v1); }
                if (v2 > b1hi) { b2hi = b1hi; b1hi = v2; i1hi = code0; }
                else           { b2hi = fmaxf(b2hi, v2); }
                if (v3 > b1hi) { b2hi = b1hi; b1hi = v3; i1hi = code0 + 1; }
                else           { b2hi = fmaxf(b2hi, v3); }
            }
        }

        // reduce across the 4 lanes sharing each row (xor 1, xor 2)
        #pragma unroll
        for (int o = 1; o <= 2; o <<= 1) {
            float ob1 = __shfl_xor_sync(0xffffffffu, b1lo, o);
            int   oi1 = __shfl_xor_sync(0xffffffffu, i1lo, o);
            float ob2 = __shfl_xor_sync(0xffffffffu, b2lo, o);
            if (ob1 > b1lo || (ob1 == b1lo && oi1 < i1lo)) {
                b2lo = fmaxf(b1lo, ob2); b1lo = ob1; i1lo = oi1;
            } else b2lo = fmaxf(b2lo, ob1);
            ob1 = __shfl_xor_sync(0xffffffffu, b1hi, o);
            oi1 = __shfl_xor_sync(0xffffffffu, i1hi, o);
            ob2 = __shfl_xor_sync(0xffffffffu, b2hi, o);
            if (ob1 > b1hi || (ob1 == b1hi && oi1 < i1hi)) {
                b2hi = fmaxf(b1hi, ob2); b1hi = ob1; i1hi = oi1;
            } else b2hi = fmaxf(b2hi, ob1);
        }

        if (tig == 0) {
            #pragma unroll
            for (int h = 0; h < 2; h++) {
                int   p  = h ? r1 : r0;
                float B1 = h ? b1hi : b1lo;
                float B2 = h ? b2hi : b2lo;
                int   I1 = h ? i1hi : i1lo;
                sk[p] = I1;
                ind_out[n0tile + p] = (float)I1;
                atomicAdd(&g_counts[I1], 1.f);
                float marg = fmaf(margc, sqrtf(norm[p]), 1e-4f);
                if (B1 - B2 <= marg) {
                    int s = atomicAdd(&g_nsusp, 1);
                    g_susp[s] = n0tile + p;
                }
            }
        }
        __syncthreads();

        // gather q -> out, diff, REDG x into g_esum (rescue patches suspects)
        {
            const int p = tid & 127;
            const int k = sk[p];
            #pragma unroll 8
            for (int j = 0; j < 32; j++) {
                int c = (tid >> 7) + 2*j;
                float q  = __ldg(&emb[c*NK + k]);
                float xv = xin[c*NHW + p];
                op[c*NHW + p] = q;
                float d = q - xv;
                ddiff = fmaf(d, d, ddiff);
                atomicAdd(&g_esum[c*NK + k], xv);
            }
        }
    }

    #pragma unroll
    for (int o = 16; o; o >>= 1) ddiff += __shfl_down_sync(0xffffffffu, ddiff, o);
    if (lid == 0) red[wid] = ddiff;
    __syncthreads();
    if (tid == 0) {
        float s = 0.f;
        #pragma unroll
        for (int w = 0; w < 8; w++) s += red[w];
        atomicAdd(&g_diff, s);
    }
}

// ---------------------------------------------------------------------------
// exact fp32 rescore for suspect points; patch out/ind/diff/esum/counts
// ---------------------------------------------------------------------------
__global__ __launch_bounds__(TPB) void vq_rescue(
    const float* __restrict__ input, const float* __restrict__ emb,
    float* __restrict__ out)
{
    const int lid = threadIdx.x & 31;
    const int gw  = blockIdx.x*(TPB/32) + (threadIdx.x >> 5);
    const int nw  = gridDim.x*(TPB/32);
    const int ns  = g_nsusp;

    for (int s = gw; s < ns; s += nw) {
        int n  = g_susp[s];
        int b  = n >> 12;
        int hw = n & 4095;
        const float* xp = input + (size_t)b*NC*NHW + hw;
        float x[NC];
        #pragma unroll 8
        for (int c = 0; c < NC; c++) x[c] = __ldg(&xp[c*NHW]);

        float best = -CUDART_INF_F;
        int   bk   = NK;
        for (int k = lid; k < NK; k += 32) {
            float sc = g_neghn[k];
            #pragma unroll 8
            for (int c = 0; c < NC; c++) sc = fmaf(x[c], __ldg(&emb[c*NK + k]), sc);
            if (sc > best) { best = sc; bk = k; }
        }
        #pragma unroll
        for (int o = 16; o; o >>= 1) {
            float ov = __shfl_down_sync(0xffffffffu, best, o);
            int   oi = __shfl_down_sync(0xffffffffu, bk, o);
            if (ov > best || (ov == best && oi < bk)) { best = ov; bk = oi; }
        }
        bk = __shfl_sync(0xffffffffu, bk, 0);

        int oldk = (int)out[OFF_IND + n];
        if (bk != oldk) {
            float dd = 0.f;
            for (int c = lid; c < NC; c += 32) {
                float qn = __ldg(&emb[c*NK + bk]);
                float qo = __ldg(&emb[c*NK + oldk]);
                float xv = x[c];
                out[OFF_OUT + (size_t)b*NC*NHW + c*NHW + hw] = qn;
                dd += (qn - xv)*(qn - xv) - (qo - xv)*(qo - xv);
                atomicAdd(&g_esum[c*NK + oldk], -xv);
                atomicAdd(&g_esum[c*NK + bk],    xv);
            }
            #pragma unroll
            for (int o = 16; o; o >>= 1) dd += __shfl_down_sync(0xffffffffu, dd, o);
            if (lid == 0) {
                atomicAdd(&g_diff, dd);
                atomicAdd(&g_counts[oldk], -1.f);
                atomicAdd(&g_counts[bk],    1.f);
                out[OFF_IND + n] = (float)bk;
            }
        }
    }
}

// ---------------------------------------------------------------------------
__global__ void vq_csum(const float* __restrict__ cs, float* __restrict__ d_out) {
    __shared__ float red[16];
    int k = threadIdx.x;  // 512
    float ncs = fmaf(cs[k], 0.99f, 0.01f*g_counts[k]);
    d_out[OFF_CS + k] = ncs;
    float v = ncs;
    #pragma unroll
    for (int o = 16; o; o >>= 1) v += __shfl_down_sync(0xffffffffu, v, o);
    if ((k & 31) == 0) red[k >> 5] = v;
    __syncthreads();
    if (k < 32) {
        float w = (k < 16) ? red[k] : 0.f;
        #pragma unroll
        for (int o = 8; o; o >>= 1) w += __shfl_down_sync(0xffffffffu, w, o);
        if (k == 0) red[0] = w;
    }
    __syncthreads();
    float tot = red[0];
    float csk = (ncs + 1e-5f) / (tot + 512.f*1e-5f) * tot;
    g_inv[k] = 1.f/csk;
    if (k == 0) d_out[OFF_DIFF] = g_diff * (1.f/(float)(NPTS*NC));
}

__global__ void vq_ema(const float* __restrict__ eavg, float* __restrict__ d_out) {
    int i = blockIdx.x*blockDim.x + threadIdx.x;   // 32768
    float na = fmaf(eavg[i], 0.99f, 0.01f*g_esum[i]);
    d_out[OFF_EAVG + i] = na;
    d_out[OFF_EMB  + i] = na * g_inv[i & 511];
}

// ---------------------------------------------------------------------------
extern "C" void kernel_launch(void* const* d_in, const int* in_sizes, int n_in,
                              void* d_out, int out_size) {
    const float* input = (const float*)d_in[0];
    const float* emb   = (const float*)d_in[1];
    const float* cs    = (const float*)d_in[2];
    const float* eavg  = (const float*)d_in[3];
    float* out = (float*)d_out;

    cudaFuncSetAttribute(vq_scores, cudaFuncAttributeMaxDynamicSharedMemorySize, A_SMEM);

    vq_prep<<<64, 512>>>(emb);
    vq_scores<<<GRID, TPB, A_SMEM>>>(input, emb, out + OFF_OUT, out + OFF_IND);
    vq_rescue<<<64, TPB>>>(input, emb, out);
    vq_csum<<<1, NK>>>(cs, out);
    vq_ema<<<NC*NK/TPB, TPB>>>(eavg, out);
}